// round 1
// baseline (speedup 1.0000x reference)
#include <cuda_runtime.h>
#include <cuda_bf16.h>

// SmoothLDDTLoss — b=2, n=4096.
// Upper-triangle tiling (sum is symmetric, diagonal excluded) -> 16.77M pairs.
// Per pair: 2 sqrt.approx + 1 ex2 (__expf) + 1 rcp (__fdividef) MUFU ops.

#define NTOK 4096
#define TILE 128
#define NTILES (NTOK / TILE)   // 32

// accumulators: [num0, den0, num1, den1]
__device__ double g_acc[4];

__global__ void init_kernel() {
    g_acc[0] = 0.0; g_acc[1] = 0.0; g_acc[2] = 0.0; g_acc[3] = 0.0;
}

__device__ __forceinline__ float fsqrt_approx(float x) {
    float r;
    asm("sqrt.approx.f32 %0, %1;" : "=f"(r) : "f"(x));
    return r;
}

__global__ void __launch_bounds__(TILE)
lddt_kernel(const float* __restrict__ pred,
            const float* __restrict__ truec,
            const int* __restrict__ is_dna,
            const int* __restrict__ is_rna,
            const int* __restrict__ cmask)
{
    const int ti = blockIdx.x;
    const int tj = blockIdx.y;
    if (ti > tj) return;                 // upper triangle only
    const int b  = blockIdx.z;

    const int tid = threadIdx.x;

    __shared__ float4 sjp[TILE];         // pred xyz, w = nuc flag
    __shared__ float4 sjt[TILE];         // true xyz, w = coords_mask

    const int base = b * NTOK;

    // stage j-tile
    {
        const int jg = base + tj * TILE + tid;
        float4 p, t;
        p.x = pred[3 * jg + 0]; p.y = pred[3 * jg + 1]; p.z = pred[3 * jg + 2];
        t.x = truec[3 * jg + 0]; t.y = truec[3 * jg + 1]; t.z = truec[3 * jg + 2];
        p.w = (is_dna[jg] != 0 || is_rna[jg] != 0) ? 1.0f : 0.0f;
        t.w = (cmask[jg] != 0) ? 1.0f : 0.0f;
        sjp[tid] = p;
        sjt[tid] = t;
    }

    // own i row
    const int ig = base + ti * TILE + tid;
    const float ipx = pred[3 * ig + 0], ipy = pred[3 * ig + 1], ipz = pred[3 * ig + 2];
    const float itx = truec[3 * ig + 0], ity = truec[3 * ig + 1], itz = truec[3 * ig + 2];
    const float nuc_i = (is_dna[ig] != 0 || is_rna[ig] != 0) ? 1.0f : 0.0f;
    const float cm_i  = (cmask[ig] != 0) ? 1.0f : 0.0f;

    __syncthreads();

    // sigmoid threshold constants: exp(-0.5), exp(-1), exp(-2), exp(-4)
    const float C0 = 0.60653066f, C1 = 0.36787944f, C2 = 0.13533528f, C3 = 0.018315639f;

    float acc_num = 0.0f;
    float acc_den = 0.0f;

    const int j0 = (ti == tj) ? (tid + 1) : 0;

    #pragma unroll 4
    for (int j = j0; j < TILE; ++j) {
        const float4 jp = sjp[j];
        const float4 jt = sjt[j];

        float dx = ipx - jp.x, dy = ipy - jp.y, dz = ipz - jp.z;
        float d2p = fmaf(dx, dx, fmaf(dy, dy, dz * dz));
        float ex = itx - jt.x, ey = ity - jt.y, ez = itz - jt.z;
        float d2t = fmaf(ex, ex, fmaf(ey, ey, ez * ez));

        // cutoff^2 = 225 or 900 (nucleotide pair)
        float cut2 = fmaf(nuc_i * jp.w, 675.0f, 225.0f);
        float cmpair = cm_i * jt.w;
        float m = (d2t < cut2) ? cmpair : 0.0f;

        float st = fsqrt_approx(d2t);
        float sp = fsqrt_approx(d2p);
        float dd = fminf(fabsf(st - sp), 20.0f);

        float e = __expf(dd);
        float b0 = fmaf(e, C0, 1.0f);
        float b1 = fmaf(e, C1, 1.0f);
        float b2 = fmaf(e, C2, 1.0f);
        float b3 = fmaf(e, C3, 1.0f);
        float p01 = b0 * b1, p23 = b2 * b3;
        float s01 = b0 + b1, s23 = b2 + b3;
        float numr = fmaf(s01, p23, s23 * p01);
        float sum4 = __fdividef(numr, p01 * p23);   // = 4 * eps

        acc_num = fmaf(sum4, m, acc_num);
        acc_den += m;
    }

    // block reduce (4 warps)
    #pragma unroll
    for (int o = 16; o > 0; o >>= 1) {
        acc_num += __shfl_xor_sync(0xFFFFFFFFu, acc_num, o);
        acc_den += __shfl_xor_sync(0xFFFFFFFFu, acc_den, o);
    }
    __shared__ float rn[4], rd[4];
    const int wid = tid >> 5;
    if ((tid & 31) == 0) { rn[wid] = acc_num; rd[wid] = acc_den; }
    __syncthreads();
    if (tid == 0) {
        float tn = rn[0] + rn[1] + rn[2] + rn[3];
        float td = rd[0] + rd[1] + rd[2] + rd[3];
        atomicAdd(&g_acc[2 * b + 0], (double)tn);
        atomicAdd(&g_acc[2 * b + 1], (double)td);
    }
}

__global__ void final_kernel(float* __restrict__ out) {
    // full-matrix sums = 2 * upper-triangle sums; eps = 0.25 * sum4
    double l0, l1;
    {
        double num = 2.0 * 0.25 * g_acc[0];
        double den = 2.0 * g_acc[1];
        if (den < 1.0) den = 1.0;
        l0 = num / den;
    }
    {
        double num = 2.0 * 0.25 * g_acc[2];
        double den = 2.0 * g_acc[3];
        if (den < 1.0) den = 1.0;
        l1 = num / den;
    }
    out[0] = (float)(1.0 - 0.5 * (l0 + l1));
}

extern "C" void kernel_launch(void* const* d_in, const int* in_sizes, int n_in,
                              void* d_out, int out_size) {
    const float* pred  = (const float*)d_in[0];
    const float* truec = (const float*)d_in[1];
    const int*   dna   = (const int*)d_in[2];
    const int*   rna   = (const int*)d_in[3];
    const int*   cm    = (const int*)d_in[4];

    init_kernel<<<1, 1>>>();
    dim3 grid(NTILES, NTILES, 2);
    lddt_kernel<<<grid, TILE>>>(pred, truec, dna, rna, cm);
    final_kernel<<<1, 1>>>((float*)d_out);
}